// round 16
// baseline (speedup 1.0000x reference)
#include <cuda_runtime.h>
#include <cuda_bf16.h>
#include <cstdint>

#define E_ 64
#define D_ 128
#define K_ 4
#define B_ 2
#define H_ 96
#define W_ 96
#define HW_ (H_*W_)
#define PAD_ 128

typedef unsigned long long ull;

// ---------------- scratch (static device globals) ----------------
__device__ float g_keys[K_*B_*E_*HW_ + 2*PAD_];
__device__ float g_proj[K_*B_*E_*HW_ + 2*PAD_];
__device__ float g_qT  [B_*HW_*64];               // queries transposed: [b][pix][e]
__device__ float g_pvh [4*B_*E_*HW_];             // conv partials, 4 D-quarters
__device__ float g_p   [B_*HW_*36];
__device__ float g_bveff[E_];
__device__ uint32_t g_wvh[8*64*72];               // packed bf16x2 conv weights (hi)
__device__ uint32_t g_wvl[8*64*72];               // (lo)

// ---------------- helpers ----------------
__device__ __forceinline__ float tanh_hw(float x) {
    float r; asm("tanh.approx.f32 %0, %1;" : "=f"(r) : "f"(x)); return r;
}
__device__ __forceinline__ unsigned bfpack2(float a, float b) {
    __nv_bfloat162 t = __floats2bfloat162_rn(a, b);
    return *(unsigned*)&t;
}
__device__ __forceinline__ void split2(float x, float y, uint32_t& h, uint32_t& l) {
    float h0 = __bfloat162float(__float2bfloat16(x));
    float h1 = __bfloat162float(__float2bfloat16(y));
    h = bfpack2(x, y);
    l = bfpack2(x - h0, y - h1);
}
__device__ __forceinline__ void mma16816(float* d, const uint32_t* a,
                                         uint32_t b0, uint32_t b1) {
    asm volatile(
        "mma.sync.aligned.m16n8k16.row.col.f32.bf16.bf16.f32 "
        "{%0,%1,%2,%3}, {%4,%5,%6,%7}, {%8,%9}, {%0,%1,%2,%3};"
        : "+f"(d[0]), "+f"(d[1]), "+f"(d[2]), "+f"(d[3])
        : "r"(a[0]), "r"(a[1]), "r"(a[2]), "r"(a[3]), "r"(b0), "r"(b1));
}
__device__ __forceinline__ void ldmat4(uint32_t& a, uint32_t& b, uint32_t& c,
                                       uint32_t& d, uint32_t saddr) {
    asm volatile("ldmatrix.sync.aligned.m8n8.x4.shared.b16 {%0,%1,%2,%3}, [%4];"
                 : "=r"(a), "=r"(b), "=r"(c), "=r"(d) : "r"(saddr));
}
__device__ __forceinline__ uint32_t smem_u32(const void* p) {
    uint32_t a;
    asm("{ .reg .u64 t; cvta.to.shared.u64 t, %1; cvt.u32.u64 %0, t; }" : "=r"(a) : "l"(p));
    return a;
}

// ---------------- single prep kernel ----------------
__global__ void prep_pack(const float* __restrict__ w_attn,
                          const float* __restrict__ w_val,
                          const float* __restrict__ b_val) {
    int o = blockIdx.x * 256 + threadIdx.x;
    int chunk = o / (64*72);
    int r = o - chunk*(64*72);
    int eo = r / 72;
    int idx = r - eo*72;
    int t = idx >> 3, cp = idx & 7;
    int c0 = chunk*16 + 2*cp;
    const float* wa = w_attn + eo * ((K_+1)*E_);
    const float* wv0 = w_val + c0*9 + t;
    float a0 = 0.f, a1 = 0.f;
    #pragma unroll 8
    for (int e = 0; e < E_; e++) {
        float w = wa[e];
        a0 = fmaf(w, wv0[e*(D_*9)], a0);
        a1 = fmaf(w, wv0[e*(D_*9) + 9], a1);
    }
    split2(a0, a1, g_wvh[o], g_wvl[o]);

    if (blockIdx.x == 0 && threadIdx.x < 64) {
        const float* wab = w_attn + threadIdx.x * ((K_+1)*E_);
        float a = 0.f;
        for (int e = 0; e < E_; e++) a = fmaf(wab[e], b_val[e], a);
        g_bveff[threadIdx.x] = a;
    }
}

// ---------------- queries via mma.sync bf16 3-term split -> g_qT ----------------
#define QA_H 0
#define QA_L 4352            // 64*68
#define QB_H 8704
#define QB_L 17408           // + 128*68
#define Q_TOT32 26112        // *4 = 104448 bytes

__global__ void __launch_bounds__(256) queries_mma(
        const float* __restrict__ df,
        const float* __restrict__ w_dec,
        const float* __restrict__ b_dec) {
    extern __shared__ uint32_t sm32[];
    uint32_t* AH = sm32 + QA_H;
    uint32_t* AL = sm32 + QA_L;
    uint32_t* BH = sm32 + QB_H;
    uint32_t* BL = sm32 + QB_L;
    float* stage = (float*)sm32;          // reused after A-preload: [128 px][68]
    uint32_t sb = smem_u32(sm32);
    int tid = threadIdx.x, wid = tid >> 5, lane = tid & 31;
    int b = blockIdx.y, pix0 = blockIdx.x * 128;

    for (int i = tid; i < 64*64; i += 256) {
        int m = i >> 6, c2 = i & 63;
        split2(w_dec[m*D_ + 2*c2], w_dec[m*D_ + 2*c2 + 1], AH[m*68 + c2], AL[m*68 + c2]);
    }
    const float* dfb = df + (size_t)b * D_ * HW_ + pix0;
    for (int i = tid; i < 128*64; i += 256) {
        int c2 = i >> 7, px = i & 127;
        float v0 = __ldg(dfb + (size_t)(2*c2)*HW_ + px);
        float v1 = __ldg(dfb + (size_t)(2*c2 + 1)*HW_ + px);
        split2(v0, v1, BH[px*68 + c2], BL[px*68 + c2]);
    }
    __syncthreads();

    int g = lane >> 2, tig = lane & 3;
    int mslab = wid & 3, nhalf = wid >> 2;
    int row0 = mslab*16 + g, row1 = row0 + 8;

    uint32_t ah[8][4], al[8][4];
    #pragma unroll
    for (int kt = 0; kt < 8; kt++) {
        int base = kt*8 + tig;
        ah[kt][0] = AH[row0*68 + base];     ah[kt][1] = AH[row1*68 + base];
        ah[kt][2] = AH[row0*68 + base + 4]; ah[kt][3] = AH[row1*68 + base + 4];
        al[kt][0] = AL[row0*68 + base];     al[kt][1] = AL[row1*68 + base];
        al[kt][2] = AL[row0*68 + base + 4]; al[kt][3] = AL[row1*68 + base + 4];
    }
    __syncthreads();   // A-preload done everywhere before stage region is reused

    int m8 = lane >> 3, r8 = lane & 7;
    uint32_t colb = ((m8 >> 1) << 3) + ((m8 & 1) << 2);
    uint32_t bhA0 = sb + (QB_H + r8*68 + colb)*4 + nhalf*8*2176;
    uint32_t blA0 = sb + (QB_L + r8*68 + colb)*4 + nhalf*8*2176;

    float bias0 = __ldg(&b_dec[row0]);
    float bias1 = __ldg(&b_dec[row1]);

    #pragma unroll
    for (int nt = 0; nt < 8; nt++) {
        uint32_t bh[16], bl[16];
        uint32_t aB = bhA0 + nt*2176;
        uint32_t aL = blA0 + nt*2176;
        ldmat4(bh[0], bh[1], bh[2], bh[3], aB);
        ldmat4(bh[4], bh[5], bh[6], bh[7], aB + 64);
        ldmat4(bh[8], bh[9], bh[10], bh[11], aB + 128);
        ldmat4(bh[12], bh[13], bh[14], bh[15], aB + 192);
        ldmat4(bl[0], bl[1], bl[2], bl[3], aL);
        ldmat4(bl[4], bl[5], bl[6], bl[7], aL + 64);
        ldmat4(bl[8], bl[9], bl[10], bl[11], aL + 128);
        ldmat4(bl[12], bl[13], bl[14], bl[15], aL + 192);

        float d[4] = {0.f, 0.f, 0.f, 0.f};
        #pragma unroll
        for (int kt = 0; kt < 8; kt++) {
            mma16816(d, ah[kt], bh[2*kt], bh[2*kt+1]);
            mma16816(d, al[kt], bh[2*kt], bh[2*kt+1]);
            mma16816(d, ah[kt], bl[2*kt], bl[2*kt+1]);
        }
        int pxl = (nhalf*8 + nt)*8 + 2*tig;
        stage[ pxl     *68 + row0] = d[0] + bias0;
        stage[(pxl + 1)*68 + row0] = d[1] + bias0;
        stage[ pxl     *68 + row1] = d[2] + bias1;
        stage[(pxl + 1)*68 + row1] = d[3] + bias1;
    }
    __syncthreads();
    // coalesced transpose-out: g_qT[(b*HW + pix0 + px)*64 + e]
    for (int i = tid; i < 128*16; i += 256) {
        int px = i >> 4, eq = i & 15;
        float4 v = *(const float4*)&stage[px*68 + eq*4];
        *(float4*)&g_qT[((size_t)b*HW_ + pix0 + px)*64 + eq*4] = v;
    }
}

// ---------------- keys + proj: 256-px tile, A fragments direct from global ----------------
#define KP_BH 0
#define KP_BL 9216           // 256*36
#define KP_TOT32 18432       // *4 = 73728 bytes

__global__ void __launch_bounds__(256) keysproj_mma(
        const float* __restrict__ contexts,
        const float* __restrict__ w_enc,
        const float* __restrict__ b_enc,
        const float* __restrict__ w_attn) {
    extern __shared__ uint32_t sm32[];
    uint32_t* BH = sm32 + KP_BH;
    uint32_t* BL = sm32 + KP_BL;
    uint32_t sb = smem_u32(sm32);
    int tid = threadIdx.x, wid = tid >> 5, lane = tid & 31;
    int kb = blockIdx.y, k = kb >> 1;
    int pix0 = blockIdx.x * 256;

    const float* ctx = contexts + (size_t)kb * E_ * HW_ + pix0;
    for (int i = tid; i < 256*32; i += 256) {
        int c2 = i >> 8, px = i & 255;
        float v0 = __ldg(ctx + (2*c2)*HW_ + px);
        float v1 = __ldg(ctx + (2*c2 + 1)*HW_ + px);
        split2(v0, v1, BH[px*36 + c2], BL[px*36 + c2]);
    }

    int g = lane >> 2, tig = lane & 3;
    int m0 = wid * 16;
    int row0 = m0 + g, row1 = m0 + g + 8;

    const float* rp0 = (row0 < 64) ? (w_enc + row0*64)
                                   : (w_attn + (row0 - 64)*((K_+1)*E_) + (k + 1)*E_);
    const float* rp1 = (row1 < 64) ? (w_enc + row1*64)
                                   : (w_attn + (row1 - 64)*((K_+1)*E_) + (k + 1)*E_);
    uint32_t ah[4][4], al[4][4];
    #pragma unroll
    for (int kt = 0; kt < 4; kt++) {
        int c0 = 2*(kt*8 + tig);
        float2 a00 = __ldg((const float2*)(rp0 + c0));
        float2 a10 = __ldg((const float2*)(rp1 + c0));
        float2 a01 = __ldg((const float2*)(rp0 + c0 + 8));
        float2 a11 = __ldg((const float2*)(rp1 + c0 + 8));
        split2(a00.x, a00.y, ah[kt][0], al[kt][0]);
        split2(a10.x, a10.y, ah[kt][1], al[kt][1]);
        split2(a01.x, a01.y, ah[kt][2], al[kt][2]);
        split2(a11.x, a11.y, ah[kt][3], al[kt][3]);
    }
    __syncthreads();

    int m8 = lane >> 3, r8 = lane & 7;
    uint32_t colb = ((m8 >> 1) << 3) + ((m8 & 1) << 2);
    uint32_t bhA0 = sb + (KP_BH + r8*36 + colb)*4;
    uint32_t blA0 = sb + (KP_BL + r8*36 + colb)*4;

    float bias0 = (row0 < 64) ? __ldg(&b_enc[row0]) : 0.f;
    float bias1 = (row1 < 64) ? __ldg(&b_enc[row1]) : 0.f;
    float* dst0 = (row0 < 64)
        ? (g_keys + PAD_ + (size_t)(kb*E_ + row0)*HW_ + pix0)
        : (g_proj + PAD_ + (size_t)(kb*E_ + row0 - 64)*HW_ + pix0);
    float* dst1 = (row1 < 64)
        ? (g_keys + PAD_ + (size_t)(kb*E_ + row1)*HW_ + pix0)
        : (g_proj + PAD_ + (size_t)(kb*E_ + row1 - 64)*HW_ + pix0);

    #pragma unroll 4
    for (int nt = 0; nt < 32; nt++) {
        uint32_t bh[8], bl[8];
        uint32_t aB = bhA0 + nt*1152;
        uint32_t aL = blA0 + nt*1152;
        ldmat4(bh[0], bh[1], bh[2], bh[3], aB);
        ldmat4(bh[4], bh[5], bh[6], bh[7], aB + 64);
        ldmat4(bl[0], bl[1], bl[2], bl[3], aL);
        ldmat4(bl[4], bl[5], bl[6], bl[7], aL + 64);

        float d[4] = {0.f, 0.f, 0.f, 0.f};
        #pragma unroll
        for (int kt = 0; kt < 4; kt++) {
            mma16816(d, ah[kt], bh[2*kt], bh[2*kt+1]);
            mma16816(d, al[kt], bh[2*kt], bh[2*kt+1]);
            mma16816(d, ah[kt], bl[2*kt], bl[2*kt+1]);
        }
        int col = nt*8 + 2*tig;
        *(float2*)&dst0[col] = make_float2(d[0] + bias0, d[1] + bias0);
        *(float2*)&dst1[col] = make_float2(d[2] + bias1, d[3] + bias1);
    }
}

// ---------------- conv 3x3 via implicit-GEMM mma.sync (D quartered) ----------------
#define CV_AH 0
#define CV_AL 4864           // 64*76
#define CV_HH 9728
#define CV_HL 13808          // + 340*12
#define CV_TOT32 17888       // *4 = 71552 bytes

__global__ void __launch_bounds__(256, 2) conv_mma(const float* __restrict__ df) {
    extern __shared__ uint32_t cs[];
    uint32_t sb = smem_u32(cs);
    int tid = threadIdx.x, wid = tid >> 5, lane = tid & 31;
    int bz = blockIdx.z;
    int b = bz >> 2, quarter = bz & 3;
    int w0 = blockIdx.x * 32, h0 = blockIdx.y * 8;
    int mslab = wid & 3, nh = wid >> 2;
    int m0 = mslab * 16;
    int g8 = lane >> 3, r8 = lane & 7;
    int tg = lane >> 2, tig = lane & 3;

    uint32_t aA = sb + (CV_AH + ((m0 + (g8 & 1)*8 + r8)*76 + (g8 >> 1)*4))*4;
    uint32_t aB = sb + CV_HH*4
                + (34 + nh*16 + (g8 >> 1)*8 + r8 + 1)*48 + (g8 & 1)*16;

    float d[16][4];
    #pragma unroll
    for (int i = 0; i < 16; i++)
        #pragma unroll
        for (int j = 0; j < 4; j++) d[i][j] = 0.f;

    for (int chunk = 0; chunk < 2; chunk++) {
        int gchunk = quarter*2 + chunk;
        int d0 = gchunk*16;
        __syncthreads();
        {
            const uint32_t* srcH = g_wvh + gchunk*4608;
            const uint32_t* srcL = g_wvl + gchunk*4608;
            for (int i = tid; i < 4608; i += 256) {
                int m = i / 72, c = i - m*72;
                cs[CV_AH + m*76 + c] = srcH[i];
                cs[CV_AL + m*76 + c] = srcL[i];
            }
        }
        {
            for (int i = tid; i < 2720; i += 256) {
                int cp = i / 340, hp = i - cp*340;
                int hy = hp / 34, hx = hp - hy*34;
                int gh = h0 + hy - 1, gw = w0 + hx - 1;
                uint32_t vh = 0, vl = 0;
                if ((unsigned)gh < H_ && (unsigned)gw < W_) {
                    const float* p = df + (size_t)(b*D_ + d0 + 2*cp)*HW_ + gh*W_ + gw;
                    split2(__ldg(p), __ldg(p + HW_), vh, vl);
                }
                cs[CV_HH + hp*12 + cp] = vh;
                cs[CV_HL + hp*12 + cp] = vl;
            }
        }
        __syncthreads();

        for (int t = 0; t < 9; t++) {
            uint32_t ah[4], al[4];
            ldmat4(ah[0], ah[1], ah[2], ah[3], aA + t*32);
            ldmat4(al[0], al[1], al[2], al[3], aA + 19456 + t*32);
            int t3 = t / 3;
            int toff = (t3*34 + (t - t3*3) - 35) * 48;
            uint32_t bbase = aB + toff;
            #pragma unroll
            for (int ntp = 0; ntp < 8; ntp++) {
                uint32_t ba = bbase + ntp*1632;
                uint32_t bh[4], bl[4];
                ldmat4(bh[0], bh[1], bh[2], bh[3], ba);
                ldmat4(bl[0], bl[1], bl[2], bl[3], ba + 16320);
                mma16816(d[ntp*2],     ah, bh[0], bh[1]);
                mma16816(d[ntp*2],     al, bh[0], bh[1]);
                mma16816(d[ntp*2],     ah, bl[0], bl[1]);
                mma16816(d[ntp*2 + 1], ah, bh[2], bh[3]);
                mma16816(d[ntp*2 + 1], al, bh[2], bh[3]);
                mma16816(d[ntp*2 + 1], ah, bl[2], bl[3]);
            }
        }
    }
    float* base = g_pvh + (size_t)quarter*(B_*E_*HW_);
    int eo0 = m0 + tg;
    #pragma unroll
    for (int ntp = 0; ntp < 8; ntp++) {
        int pixrow = (h0 + ntp)*W_ + w0 + nh*16;
        #pragma unroll
        for (int hb = 0; hb < 2; hb++) {
            float* dd = d[ntp*2 + hb];
            int col = pixrow + hb*8 + 2*tig;
            *(float2*)&base[(b*E_ + eo0    )*HW_ + col] = make_float2(dd[0], dd[1]);
            *(float2*)&base[(b*E_ + eo0 + 8)*HW_ + col] = make_float2(dd[2], dd[3]);
        }
    }
}

// ---------------- attention: transposed key halo + float4 loads ----------------
// kh_t[pos 360][e 64 + 4 pad]; pos = hy*36 + hx (10 rows x 36 cols, 34 used).
#define KHT_STRIDE 68
#define ATTN_SM32 (360*KHT_STRIDE + 64)   // u32 words

__global__ void __launch_bounds__(256) attn_kernel(const float* __restrict__ w_agg) {
    extern __shared__ float asm_[];
    float* kh_t = asm_;
    float* swa = asm_ + 360*KHT_STRIDE;   // offset 97920 B, 16B aligned
    int tid = threadIdx.x;
    int kb = blockIdx.z;
    int b = kb & 1, k = kb >> 1;
    int w0 = blockIdx.x * 32, h0 = blockIdx.y * 8;
    int pxc = tid & 31, py = tid >> 5;

    if (tid < 64) swa[tid] = w_agg[tid];
    const float* keyb = g_keys + PAD_ + (size_t)(kb*E_)*HW_;
    for (int i = tid; i < 64*90; i += 256) {
        int e = i / 90, qp = i - e*90;
        int pos0 = qp*4;
        int hy = pos0 / 36, hx = pos0 - hy*36;
        int pixg = (h0 + hy - 1)*W_ + (w0 + hx - 1);  // pads cover over/underrun
        const float* src = keyb + (size_t)e*HW_ + pixg;
        #pragma unroll
        for (int r = 0; r < 4; r++)
            kh_t[(pos0 + r)*KHT_STRIDE + e] = src[r];
    }
    __syncthreads();

    int h = h0 + py, w = w0 + pxc;
    int pix = h*W_ + w;
    const float4* qT = (const float4*)(g_qT + ((size_t)b*HW_ + pix)*64);

    float s[9];
    #pragma unroll
    for (int n = 0; n < 9; n++) s[n] = 0.f;

    int posc = py*36 + pxc;   // corner (dy=0,dx=0)
    for (int eq = 0; eq < 16; eq++) {
        float4 q4 = __ldg(qT + eq);
        float4 w4 = *(const float4*)&swa[eq*4];
        #pragma unroll
        for (int dy = 0; dy < 3; dy++) {
            #pragma unroll
            for (int dx = 0; dx < 3; dx++) {
                float4 k4 = *(const float4*)&kh_t[(posc + dy*36 + dx)*KHT_STRIDE + eq*4];
                float acc = s[dy*3 + dx];
                acc = fmaf(w4.x, tanh_hw(q4.x + k4.x), acc);
                acc = fmaf(w4.y, tanh_hw(q4.y + k4.y), acc);
                acc = fmaf(w4.z, tanh_hw(q4.z + k4.z), acc);
                acc = fmaf(w4.w, tanh_hw(q4.w + k4.w), acc);
                s[dy*3 + dx] = acc;
            }
        }
    }
    bool vt = h > 0, vb = h < H_-1, vl = w > 0, vr = w < W_-1;
    bool valid[9] = {vt&&vl, vt, vt&&vr, vl, true, vr, vb&&vl, vb, vb&&vr};
    float p[9], sum = 0.f;
    #pragma unroll
    for (int n = 0; n < 9; n++) {
        p[n] = valid[n] ? __expf(s[n]) : 0.f;
        sum += p[n];
    }
    float inv = 1.0f / sum;
    float* pd = g_p + (size_t)(b*HW_ + pix)*36 + k*9;
    #pragma unroll
    for (int n = 0; n < 9; n++) pd[n] = p[n] * inv;
}

// ---------------- output: windowed loads, 4 px x 2 eo per thread ----------------
__global__ void __launch_bounds__(256) out_kernel(const float* __restrict__ b_attn,
                                                  float* __restrict__ out) {
    __shared__ float sp_t[36][36];
    int tid = threadIdx.x;
    int pixg0 = blockIdx.x * 32;
    int lane = tid & 31, ty = tid >> 5;

    for (int i = tid; i < 32*36; i += 256) {
        int a = i & 31, j = i >> 5;
        sp_t[j][a] = g_p[(size_t)(pixg0 + a)*36 + j];
    }
    __syncthreads();

    int pxg = lane & 7, es = lane >> 3;
    int pg = pixg0 + pxg*4;
    int b = pg / HW_;
    int pix = pg - b*HW_;
    int eo0 = ty*8 + es*2;

    float acc[2][4];
    #pragma unroll
    for (int e2 = 0; e2 < 2; e2++) {
        size_t idx = (size_t)(b*E_ + eo0 + e2)*HW_ + pix;
        float4 v0 = *(const float4*)&g_pvh[idx];
        float4 v1 = *(const float4*)&g_pvh[(size_t)(B_*E_*HW_) + idx];
        float4 v2 = *(const float4*)&g_pvh[(size_t)(2*B_*E_*HW_) + idx];
        float4 v3 = *(const float4*)&g_pvh[(size_t)(3*B_*E_*HW_) + idx];
        acc[e2][0] = (v0.x + v1.x) + (v2.x + v3.x);
        acc[e2][1] = (v0.y + v1.y) + (v2.y + v3.y);
        acc[e2][2] = (v0.z + v1.z) + (v2.z + v3.z);
        acc[e2][3] = (v0.w + v1.w) + (v2.w + v3.w);
    }

    #pragma unroll
    for (int k = 0; k < K_; k++) {
        float4 pk[9];
        #pragma unroll
        for (int n = 0; n < 9; n++)
            pk[n] = *(const float4*)&sp_t[k*9 + n][pxg*4];

        #pragma unroll
        for (int e2 = 0; e2 < 2; e2++) {
            const float* pj = g_proj + PAD_
                + (size_t)((k*B_ + b)*E_ + eo0 + e2)*HW_ + pix;
            #pragma unroll
            for (int dy = 0; dy < 3; dy++) {
                const float* pr = pj + (dy - 1)*W_;
                float4 m = *(const float4*)pr;
                float w[6];
                w[0] = __ldg(pr - 1); w[1] = m.x; w[2] = m.y;
                w[3] = m.z; w[4] = m.w; w[5] = __ldg(pr + 4);
                #pragma unroll
                for (int dx = 0; dx < 3; dx++) {
                    const float* pkn = (const float*)&pk[dy*3 + dx];
                    acc[e2][0] = fmaf(pkn[0], w[0 + dx], acc[e2][0]);
                    acc[e2][1] = fmaf(pkn[1], w[1 + dx], acc[e2][1]);
                    acc[e2][2] = fmaf(pkn[2], w[2 + dx], acc[e2][2]);
                    acc[e2][3] = fmaf(pkn[3], w[3 + dx], acc[e2][3]);
                }
            }
        }
    }
    #pragma unroll
    for (int e2 = 0; e2 < 2; e2++) {
        float bias = __ldg(&g_bveff[eo0 + e2]) + __ldg(&b_attn[eo0 + e2]);
        float4 v;
        v.x = acc[e2][0] + bias; v.y = acc[e2][1] + bias;
        v.z = acc[e2][2] + bias; v.w = acc[e2][3] + bias;
        v.x = (v.x >= 0.f) ? v.x : 0.2f*v.x;
        v.y = (v.y >= 0.f) ? v.y : 0.2f*v.y;
        v.z = (v.z >= 0.f) ? v.z : 0.2f*v.z;
        v.w = (v.w >= 0.f) ? v.w : 0.2f*v.w;
        *(float4*)&out[(size_t)(b*E_ + eo0 + e2)*HW_ + pix] = v;
    }
}

// ---------------- launch: fork-join DAG across 3 streams ----------------
extern "C" void kernel_launch(void* const* d_in, const int* in_sizes, int n_in,
                              void* d_out, int out_size) {
    const float* contexts = (const float*)d_in[0];
    const float* df       = (const float*)d_in[1];
    const float* w_enc    = (const float*)d_in[2];
    const float* b_enc    = (const float*)d_in[3];
    const float* w_dec    = (const float*)d_in[4];
    const float* b_dec    = (const float*)d_in[5];
    const float* w_agg    = (const float*)d_in[6];
    // d_in[7] = b_agg: cancels in softmax, unused
    const float* w_val    = (const float*)d_in[8];
    const float* b_val    = (const float*)d_in[9];
    const float* w_attn   = (const float*)d_in[10];
    const float* b_attn   = (const float*)d_in[11];
    float* out = (float*)d_out;

    static cudaStream_t s1 = nullptr, s2 = nullptr;
    static cudaEvent_t eF = nullptr, eQ = nullptr, eC = nullptr;
    static bool attrs_set = false;
    if (s1 == nullptr) {
        cudaStreamCreateWithFlags(&s1, cudaStreamNonBlocking);
        cudaStreamCreateWithFlags(&s2, cudaStreamNonBlocking);
        cudaEventCreateWithFlags(&eF, cudaEventDisableTiming);
        cudaEventCreateWithFlags(&eQ, cudaEventDisableTiming);
        cudaEventCreateWithFlags(&eC, cudaEventDisableTiming);
    }

    int smq = Q_TOT32 * 4;
    int smk = KP_TOT32 * 4;
    int smc = CV_TOT32 * 4;
    int sma = ATTN_SM32 * 4;
    if (!attrs_set) {
        cudaFuncSetAttribute(queries_mma,   cudaFuncAttributeMaxDynamicSharedMemorySize, smq);
        cudaFuncSetAttribute(keysproj_mma,  cudaFuncAttributeMaxDynamicSharedMemorySize, smk);
        cudaFuncSetAttribute(conv_mma,      cudaFuncAttributeMaxDynamicSharedMemorySize, smc);
        cudaFuncSetAttribute(attn_kernel,   cudaFuncAttributeMaxDynamicSharedMemorySize, sma);
        attrs_set = true;
    }

    // fork
    cudaEventRecord(eF, 0);
    cudaStreamWaitEvent(s1, eF, 0);
    cudaStreamWaitEvent(s2, eF, 0);

    // branch s1: conv chain (independent of attention path)
    prep_pack<<<144, 256, 0, s1>>>(w_attn, w_val, b_val);
    conv_mma<<<dim3(3, 12, B_*4), 256, smc, s1>>>(df);
    cudaEventRecord(eC, s1);

    // branch s2: queries
    queries_mma<<<dim3(HW_/128, B_), 256, smq, s2>>>(df, w_dec, b_dec);
    cudaEventRecord(eQ, s2);

    // main stream: keysproj -> (join queries) attn -> (join conv) out
    keysproj_mma<<<dim3(HW_/256, K_*B_), 256, smk>>>(contexts, w_enc, b_enc, w_attn);
    cudaStreamWaitEvent(0, eQ, 0);
    attn_kernel<<<dim3(3, 12, K_*B_), 256, sma>>>(w_agg);
    cudaStreamWaitEvent(0, eC, 0);
    out_kernel<<<(B_*HW_)/32, 256>>>(b_attn, out);
}

// round 17
// speedup vs baseline: 1.0887x; 1.0887x over previous
#include <cuda_runtime.h>
#include <cuda_bf16.h>
#include <cstdint>

#define E_ 64
#define D_ 128
#define K_ 4
#define B_ 2
#define H_ 96
#define W_ 96
#define HW_ (H_*W_)
#define PAD_ 128

typedef unsigned long long ull;

// ---------------- scratch (static device globals) ----------------
__device__ float g_keys[K_*B_*E_*HW_ + 2*PAD_];
__device__ float g_proj[K_*B_*E_*HW_ + 2*PAD_];
__device__ float g_q   [B_*E_*HW_];
__device__ float g_pvh [4*B_*E_*HW_];             // conv partials, 4 D-quarters
__device__ float g_p   [B_*HW_*36];
__device__ float g_bveff[E_];
__device__ uint32_t g_wvh[8*64*72];               // packed bf16x2 conv weights (hi)
__device__ uint32_t g_wvl[8*64*72];               // (lo)

// ---------------- helpers ----------------
__device__ __forceinline__ float tanh_hw(float x) {
    float r; asm("tanh.approx.f32 %0, %1;" : "=f"(r) : "f"(x)); return r;
}
__device__ __forceinline__ unsigned bfpack2(float a, float b) {
    __nv_bfloat162 t = __floats2bfloat162_rn(a, b);
    return *(unsigned*)&t;
}
__device__ __forceinline__ void split2(float x, float y, uint32_t& h, uint32_t& l) {
    float h0 = __bfloat162float(__float2bfloat16(x));
    float h1 = __bfloat162float(__float2bfloat16(y));
    h = bfpack2(x, y);
    l = bfpack2(x - h0, y - h1);
}
__device__ __forceinline__ void mma16816(float* d, const uint32_t* a,
                                         uint32_t b0, uint32_t b1) {
    asm volatile(
        "mma.sync.aligned.m16n8k16.row.col.f32.bf16.bf16.f32 "
        "{%0,%1,%2,%3}, {%4,%5,%6,%7}, {%8,%9}, {%0,%1,%2,%3};"
        : "+f"(d[0]), "+f"(d[1]), "+f"(d[2]), "+f"(d[3])
        : "r"(a[0]), "r"(a[1]), "r"(a[2]), "r"(a[3]), "r"(b0), "r"(b1));
}
__device__ __forceinline__ void ldmat4(uint32_t& a, uint32_t& b, uint32_t& c,
                                       uint32_t& d, uint32_t saddr) {
    asm volatile("ldmatrix.sync.aligned.m8n8.x4.shared.b16 {%0,%1,%2,%3}, [%4];"
                 : "=r"(a), "=r"(b), "=r"(c), "=r"(d) : "r"(saddr));
}
__device__ __forceinline__ uint32_t smem_u32(const void* p) {
    uint32_t a;
    asm("{ .reg .u64 t; cvta.to.shared.u64 t, %1; cvt.u32.u64 %0, t; }" : "=r"(a) : "l"(p));
    return a;
}

// ---------------- single prep kernel ----------------
__global__ void prep_pack(const float* __restrict__ w_attn,
                          const float* __restrict__ w_val,
                          const float* __restrict__ b_val) {
    int o = blockIdx.x * 256 + threadIdx.x;
    int chunk = o / (64*72);
    int r = o - chunk*(64*72);
    int eo = r / 72;
    int idx = r - eo*72;
    int t = idx >> 3, cp = idx & 7;
    int c0 = chunk*16 + 2*cp;
    const float* wa = w_attn + eo * ((K_+1)*E_);
    const float* wv0 = w_val + c0*9 + t;
    float a0 = 0.f, a1 = 0.f;
    #pragma unroll 8
    for (int e = 0; e < E_; e++) {
        float w = wa[e];
        a0 = fmaf(w, wv0[e*(D_*9)], a0);
        a1 = fmaf(w, wv0[e*(D_*9) + 9], a1);
    }
    split2(a0, a1, g_wvh[o], g_wvl[o]);

    if (blockIdx.x == 0 && threadIdx.x < 64) {
        const float* wab = w_attn + threadIdx.x * ((K_+1)*E_);
        float a = 0.f;
        for (int e = 0; e < E_; e++) a = fmaf(wab[e], b_val[e], a);
        g_bveff[threadIdx.x] = a;
    }
}

// ---------------- queries via mma.sync bf16 3-term split ----------------
#define QA_H 0
#define QA_L 4352            // 64*68
#define QB_H 8704
#define QB_L 17408           // + 128*68
#define Q_TOT32 26112        // *4 = 104448 bytes

__global__ void __launch_bounds__(256) queries_mma(
        const float* __restrict__ df,
        const float* __restrict__ w_dec,
        const float* __restrict__ b_dec) {
    extern __shared__ uint32_t sm32[];
    uint32_t* AH = sm32 + QA_H;
    uint32_t* AL = sm32 + QA_L;
    uint32_t* BH = sm32 + QB_H;
    uint32_t* BL = sm32 + QB_L;
    uint32_t sb = smem_u32(sm32);
    int tid = threadIdx.x, wid = tid >> 5, lane = tid & 31;
    int b = blockIdx.y, pix0 = blockIdx.x * 128;

    for (int i = tid; i < 64*64; i += 256) {
        int m = i >> 6, c2 = i & 63;
        split2(w_dec[m*D_ + 2*c2], w_dec[m*D_ + 2*c2 + 1], AH[m*68 + c2], AL[m*68 + c2]);
    }
    const float* dfb = df + (size_t)b * D_ * HW_ + pix0;
    for (int i = tid; i < 128*64; i += 256) {
        int c2 = i >> 7, px = i & 127;
        float v0 = __ldg(dfb + (size_t)(2*c2)*HW_ + px);
        float v1 = __ldg(dfb + (size_t)(2*c2 + 1)*HW_ + px);
        split2(v0, v1, BH[px*68 + c2], BL[px*68 + c2]);
    }
    __syncthreads();

    int g = lane >> 2, tig = lane & 3;
    int mslab = wid & 3, nhalf = wid >> 2;
    int row0 = mslab*16 + g, row1 = row0 + 8;

    uint32_t ah[8][4], al[8][4];
    #pragma unroll
    for (int kt = 0; kt < 8; kt++) {
        int base = kt*8 + tig;
        ah[kt][0] = AH[row0*68 + base];     ah[kt][1] = AH[row1*68 + base];
        ah[kt][2] = AH[row0*68 + base + 4]; ah[kt][3] = AH[row1*68 + base + 4];
        al[kt][0] = AL[row0*68 + base];     al[kt][1] = AL[row1*68 + base];
        al[kt][2] = AL[row0*68 + base + 4]; al[kt][3] = AL[row1*68 + base + 4];
    }

    int m8 = lane >> 3, r8 = lane & 7;
    uint32_t colb = ((m8 >> 1) << 3) + ((m8 & 1) << 2);
    uint32_t bhA0 = sb + (QB_H + r8*68 + colb)*4 + nhalf*8*2176;
    uint32_t blA0 = sb + (QB_L + r8*68 + colb)*4 + nhalf*8*2176;

    float bias0 = __ldg(&b_dec[row0]);
    float bias1 = __ldg(&b_dec[row1]);
    float* dst0 = g_q + (size_t)(b*E_ + row0)*HW_ + pix0;
    float* dst1 = g_q + (size_t)(b*E_ + row1)*HW_ + pix0;

    #pragma unroll
    for (int nt = 0; nt < 8; nt++) {
        uint32_t bh[16], bl[16];
        uint32_t aB = bhA0 + nt*2176;
        uint32_t aL = blA0 + nt*2176;
        ldmat4(bh[0], bh[1], bh[2], bh[3], aB);
        ldmat4(bh[4], bh[5], bh[6], bh[7], aB + 64);
        ldmat4(bh[8], bh[9], bh[10], bh[11], aB + 128);
        ldmat4(bh[12], bh[13], bh[14], bh[15], aB + 192);
        ldmat4(bl[0], bl[1], bl[2], bl[3], aL);
        ldmat4(bl[4], bl[5], bl[6], bl[7], aL + 64);
        ldmat4(bl[8], bl[9], bl[10], bl[11], aL + 128);
        ldmat4(bl[12], bl[13], bl[14], bl[15], aL + 192);

        float d[4] = {0.f, 0.f, 0.f, 0.f};
        #pragma unroll
        for (int kt = 0; kt < 8; kt++) {
            mma16816(d, ah[kt], bh[2*kt], bh[2*kt+1]);
            mma16816(d, al[kt], bh[2*kt], bh[2*kt+1]);
            mma16816(d, ah[kt], bl[2*kt], bl[2*kt+1]);
        }
        int col = (nhalf*8 + nt)*8 + 2*tig;
        *(float2*)&dst0[col] = make_float2(d[0] + bias0, d[1] + bias0);
        *(float2*)&dst1[col] = make_float2(d[2] + bias1, d[3] + bias1);
    }
}

// ---------------- keys + proj: 256-px tile, A fragments direct from global ----------------
#define KP_BH 0
#define KP_BL 9216           // 256*36
#define KP_TOT32 18432       // *4 = 73728 bytes

__global__ void __launch_bounds__(256) keysproj_mma(
        const float* __restrict__ contexts,
        const float* __restrict__ w_enc,
        const float* __restrict__ b_enc,
        const float* __restrict__ w_attn) {
    extern __shared__ uint32_t sm32[];
    uint32_t* BH = sm32 + KP_BH;
    uint32_t* BL = sm32 + KP_BL;
    uint32_t sb = smem_u32(sm32);
    int tid = threadIdx.x, wid = tid >> 5, lane = tid & 31;
    int kb = blockIdx.y, k = kb >> 1;
    int pix0 = blockIdx.x * 256;

    const float* ctx = contexts + (size_t)kb * E_ * HW_ + pix0;
    for (int i = tid; i < 256*32; i += 256) {
        int c2 = i >> 8, px = i & 255;
        float v0 = __ldg(ctx + (2*c2)*HW_ + px);
        float v1 = __ldg(ctx + (2*c2 + 1)*HW_ + px);
        split2(v0, v1, BH[px*36 + c2], BL[px*36 + c2]);
    }

    int g = lane >> 2, tig = lane & 3;
    int m0 = wid * 16;
    int row0 = m0 + g, row1 = m0 + g + 8;

    const float* rp0 = (row0 < 64) ? (w_enc + row0*64)
                                   : (w_attn + (row0 - 64)*((K_+1)*E_) + (k + 1)*E_);
    const float* rp1 = (row1 < 64) ? (w_enc + row1*64)
                                   : (w_attn + (row1 - 64)*((K_+1)*E_) + (k + 1)*E_);
    uint32_t ah[4][4], al[4][4];
    #pragma unroll
    for (int kt = 0; kt < 4; kt++) {
        int c0 = 2*(kt*8 + tig);
        float2 a00 = __ldg((const float2*)(rp0 + c0));
        float2 a10 = __ldg((const float2*)(rp1 + c0));
        float2 a01 = __ldg((const float2*)(rp0 + c0 + 8));
        float2 a11 = __ldg((const float2*)(rp1 + c0 + 8));
        split2(a00.x, a00.y, ah[kt][0], al[kt][0]);
        split2(a10.x, a10.y, ah[kt][1], al[kt][1]);
        split2(a01.x, a01.y, ah[kt][2], al[kt][2]);
        split2(a11.x, a11.y, ah[kt][3], al[kt][3]);
    }
    __syncthreads();

    int m8 = lane >> 3, r8 = lane & 7;
    uint32_t colb = ((m8 >> 1) << 3) + ((m8 & 1) << 2);
    uint32_t bhA0 = sb + (KP_BH + r8*36 + colb)*4;
    uint32_t blA0 = sb + (KP_BL + r8*36 + colb)*4;

    float bias0 = (row0 < 64) ? __ldg(&b_enc[row0]) : 0.f;
    float bias1 = (row1 < 64) ? __ldg(&b_enc[row1]) : 0.f;
    float* dst0 = (row0 < 64)
        ? (g_keys + PAD_ + (size_t)(kb*E_ + row0)*HW_ + pix0)
        : (g_proj + PAD_ + (size_t)(kb*E_ + row0 - 64)*HW_ + pix0);
    float* dst1 = (row1 < 64)
        ? (g_keys + PAD_ + (size_t)(kb*E_ + row1)*HW_ + pix0)
        : (g_proj + PAD_ + (size_t)(kb*E_ + row1 - 64)*HW_ + pix0);

    #pragma unroll 4
    for (int nt = 0; nt < 32; nt++) {
        uint32_t bh[8], bl[8];
        uint32_t aB = bhA0 + nt*1152;
        uint32_t aL = blA0 + nt*1152;
        ldmat4(bh[0], bh[1], bh[2], bh[3], aB);
        ldmat4(bh[4], bh[5], bh[6], bh[7], aB + 64);
        ldmat4(bl[0], bl[1], bl[2], bl[3], aL);
        ldmat4(bl[4], bl[5], bl[6], bl[7], aL + 64);

        float d[4] = {0.f, 0.f, 0.f, 0.f};
        #pragma unroll
        for (int kt = 0; kt < 4; kt++) {
            mma16816(d, ah[kt], bh[2*kt], bh[2*kt+1]);
            mma16816(d, al[kt], bh[2*kt], bh[2*kt+1]);
            mma16816(d, ah[kt], bl[2*kt], bl[2*kt+1]);
        }
        int col = nt*8 + 2*tig;
        *(float2*)&dst0[col] = make_float2(d[0] + bias0, d[1] + bias0);
        *(float2*)&dst1[col] = make_float2(d[2] + bias1, d[3] + bias1);
    }
}

// ---------------- conv 3x3 via implicit-GEMM mma.sync (D quartered) ----------------
#define CV_AH 0
#define CV_AL 4864           // 64*76
#define CV_HH 9728
#define CV_HL 13808          // + 340*12
#define CV_TOT32 17888       // *4 = 71552 bytes

__global__ void __launch_bounds__(256, 2) conv_mma(const float* __restrict__ df) {
    extern __shared__ uint32_t cs[];
    uint32_t sb = smem_u32(cs);
    int tid = threadIdx.x, wid = tid >> 5, lane = tid & 31;
    int bz = blockIdx.z;
    int b = bz >> 2, quarter = bz & 3;
    int w0 = blockIdx.x * 32, h0 = blockIdx.y * 8;
    int mslab = wid & 3, nh = wid >> 2;
    int m0 = mslab * 16;
    int g8 = lane >> 3, r8 = lane & 7;
    int tg = lane >> 2, tig = lane & 3;

    uint32_t aA = sb + (CV_AH + ((m0 + (g8 & 1)*8 + r8)*76 + (g8 >> 1)*4))*4;
    uint32_t aB = sb + CV_HH*4
                + (34 + nh*16 + (g8 >> 1)*8 + r8 + 1)*48 + (g8 & 1)*16;

    float d[16][4];
    #pragma unroll
    for (int i = 0; i < 16; i++)
        #pragma unroll
        for (int j = 0; j < 4; j++) d[i][j] = 0.f;

    for (int chunk = 0; chunk < 2; chunk++) {
        int gchunk = quarter*2 + chunk;
        int d0 = gchunk*16;
        __syncthreads();
        {
            const uint32_t* srcH = g_wvh + gchunk*4608;
            const uint32_t* srcL = g_wvl + gchunk*4608;
            for (int i = tid; i < 4608; i += 256) {
                int m = i / 72, c = i - m*72;
                cs[CV_AH + m*76 + c] = srcH[i];
                cs[CV_AL + m*76 + c] = srcL[i];
            }
        }
        {
            for (int i = tid; i < 2720; i += 256) {
                int cp = i / 340, hp = i - cp*340;
                int hy = hp / 34, hx = hp - hy*34;
                int gh = h0 + hy - 1, gw = w0 + hx - 1;
                uint32_t vh = 0, vl = 0;
                if ((unsigned)gh < H_ && (unsigned)gw < W_) {
                    const float* p = df + (size_t)(b*D_ + d0 + 2*cp)*HW_ + gh*W_ + gw;
                    split2(__ldg(p), __ldg(p + HW_), vh, vl);
                }
                cs[CV_HH + hp*12 + cp] = vh;
                cs[CV_HL + hp*12 + cp] = vl;
            }
        }
        __syncthreads();

        for (int t = 0; t < 9; t++) {
            uint32_t ah[4], al[4];
            ldmat4(ah[0], ah[1], ah[2], ah[3], aA + t*32);
            ldmat4(al[0], al[1], al[2], al[3], aA + 19456 + t*32);
            int t3 = t / 3;
            int toff = (t3*34 + (t - t3*3) - 35) * 48;
            uint32_t bbase = aB + toff;
            #pragma unroll
            for (int ntp = 0; ntp < 8; ntp++) {
                uint32_t ba = bbase + ntp*1632;
                uint32_t bh[4], bl[4];
                ldmat4(bh[0], bh[1], bh[2], bh[3], ba);
                ldmat4(bl[0], bl[1], bl[2], bl[3], ba + 16320);
                mma16816(d[ntp*2],     ah, bh[0], bh[1]);
                mma16816(d[ntp*2],     al, bh[0], bh[1]);
                mma16816(d[ntp*2],     ah, bl[0], bl[1]);
                mma16816(d[ntp*2 + 1], ah, bh[2], bh[3]);
                mma16816(d[ntp*2 + 1], al, bh[2], bh[3]);
                mma16816(d[ntp*2 + 1], ah, bl[2], bl[3]);
            }
        }
    }
    float* base = g_pvh + (size_t)quarter*(B_*E_*HW_);
    int eo0 = m0 + tg;
    #pragma unroll
    for (int ntp = 0; ntp < 8; ntp++) {
        int pixrow = (h0 + ntp)*W_ + w0 + nh*16;
        #pragma unroll
        for (int hb = 0; hb < 2; hb++) {
            float* dd = d[ntp*2 + hb];
            int col = pixrow + hb*8 + 2*tig;
            *(float2*)&base[(b*E_ + eo0    )*HW_ + col] = make_float2(dd[0], dd[1]);
            *(float2*)&base[(b*E_ + eo0 + 8)*HW_ + col] = make_float2(dd[2], dd[3]);
        }
    }
}

// ---------------- attention: smem-tiled keys halo ----------------
#define KH_STRIDE 344
__global__ void __launch_bounds__(256) attn_kernel(const float* __restrict__ w_agg) {
    extern __shared__ float asm_[];
    float* kh = asm_;                  // [64 e][stride 344]
    float* swa = asm_ + 64*KH_STRIDE;  // [64]
    int tid = threadIdx.x;
    int kb = blockIdx.z;
    int b = kb & 1, k = kb >> 1;
    int w0 = blockIdx.x * 32, h0 = blockIdx.y * 8;
    int pxc = tid & 31, py = tid >> 5;

    if (tid < 64) swa[tid] = w_agg[tid];
    const float* keyb = g_keys + PAD_ + (size_t)(kb*E_)*HW_;
    for (int i = tid; i < 64*340; i += 256) {
        int e = i / 340, r = i - e*340;
        int hy = r / 34, hx = r - hy*34;
        int pix = (h0 + hy - 1)*W_ + (w0 + hx - 1);   // pad covers OOB
        kh[e*KH_STRIDE + r] = keyb[(size_t)e*HW_ + pix];
    }
    __syncthreads();

    int h = h0 + py, w = w0 + pxc;
    int pix = h*W_ + w;
    const float* qb = g_q + (size_t)(b*E_)*HW_ + pix;
    const float* khc = kh + (py + 1)*34 + (pxc + 1);

    float s[9];
    #pragma unroll
    for (int n = 0; n < 9; n++) s[n] = 0.f;

    #pragma unroll 4
    for (int e = 0; e < 64; e++) {
        float q = __ldg(qb + (size_t)e*HW_);
        float wa = swa[e];
        const float* kp = khc + e*KH_STRIDE;
        float t0 = tanh_hw(q + kp[-35]); float t1 = tanh_hw(q + kp[-34]);
        float t2 = tanh_hw(q + kp[-33]); float t3 = tanh_hw(q + kp[-1]);
        float t4 = tanh_hw(q + kp[0]);   float t5 = tanh_hw(q + kp[1]);
        float t6 = tanh_hw(q + kp[33]);  float t7 = tanh_hw(q + kp[34]);
        float t8 = tanh_hw(q + kp[35]);
        s[0] = fmaf(wa, t0, s[0]); s[1] = fmaf(wa, t1, s[1]);
        s[2] = fmaf(wa, t2, s[2]); s[3] = fmaf(wa, t3, s[3]);
        s[4] = fmaf(wa, t4, s[4]); s[5] = fmaf(wa, t5, s[5]);
        s[6] = fmaf(wa, t6, s[6]); s[7] = fmaf(wa, t7, s[7]);
        s[8] = fmaf(wa, t8, s[8]);
    }
    bool vt = h > 0, vb = h < H_-1, vl = w > 0, vr = w < W_-1;
    bool valid[9] = {vt&&vl, vt, vt&&vr, vl, true, vr, vb&&vl, vb, vb&&vr};
    float p[9], sum = 0.f;
    #pragma unroll
    for (int n = 0; n < 9; n++) {
        p[n] = valid[n] ? __expf(s[n]) : 0.f;
        sum += p[n];
    }
    float inv = 1.0f / sum;
    float* pd = g_p + (size_t)(b*HW_ + pix)*36 + k*9;
    #pragma unroll
    for (int n = 0; n < 9; n++) pd[n] = p[n] * inv;
}

// ---------------- output: windowed loads, 4 px x 2 eo per thread ----------------
__global__ void __launch_bounds__(256) out_kernel(const float* __restrict__ b_attn,
                                                  float* __restrict__ out) {
    __shared__ float sp_t[36][36];
    int tid = threadIdx.x;
    int pixg0 = blockIdx.x * 32;
    int lane = tid & 31, ty = tid >> 5;

    for (int i = tid; i < 32*36; i += 256) {
        int a = i & 31, j = i >> 5;
        sp_t[j][a] = g_p[(size_t)(pixg0 + a)*36 + j];
    }
    __syncthreads();

    int pxg = lane & 7, es = lane >> 3;
    int pg = pixg0 + pxg*4;
    int b = pg / HW_;
    int pix = pg - b*HW_;
    int eo0 = ty*8 + es*2;

    float acc[2][4];
    #pragma unroll
    for (int e2 = 0; e2 < 2; e2++) {
        size_t idx = (size_t)(b*E_ + eo0 + e2)*HW_ + pix;
        float4 v0 = *(const float4*)&g_pvh[idx];
        float4 v1 = *(const float4*)&g_pvh[(size_t)(B_*E_*HW_) + idx];
        float4 v2 = *(const float4*)&g_pvh[(size_t)(2*B_*E_*HW_) + idx];
        float4 v3 = *(const float4*)&g_pvh[(size_t)(3*B_*E_*HW_) + idx];
        acc[e2][0] = (v0.x + v1.x) + (v2.x + v3.x);
        acc[e2][1] = (v0.y + v1.y) + (v2.y + v3.y);
        acc[e2][2] = (v0.z + v1.z) + (v2.z + v3.z);
        acc[e2][3] = (v0.w + v1.w) + (v2.w + v3.w);
    }

    #pragma unroll
    for (int k = 0; k < K_; k++) {
        float4 pk[9];
        #pragma unroll
        for (int n = 0; n < 9; n++)
            pk[n] = *(const float4*)&sp_t[k*9 + n][pxg*4];

        #pragma unroll
        for (int e2 = 0; e2 < 2; e2++) {
            const float* pj = g_proj + PAD_
                + (size_t)((k*B_ + b)*E_ + eo0 + e2)*HW_ + pix;
            #pragma unroll
            for (int dy = 0; dy < 3; dy++) {
                const float* pr = pj + (dy - 1)*W_;
                float4 m = *(const float4*)pr;
                float w[6];
                w[0] = __ldg(pr - 1); w[1] = m.x; w[2] = m.y;
                w[3] = m.z; w[4] = m.w; w[5] = __ldg(pr + 4);
                #pragma unroll
                for (int dx = 0; dx < 3; dx++) {
                    const float* pkn = (const float*)&pk[dy*3 + dx];
                    acc[e2][0] = fmaf(pkn[0], w[0 + dx], acc[e2][0]);
                    acc[e2][1] = fmaf(pkn[1], w[1 + dx], acc[e2][1]);
                    acc[e2][2] = fmaf(pkn[2], w[2 + dx], acc[e2][2]);
                    acc[e2][3] = fmaf(pkn[3], w[3 + dx], acc[e2][3]);
                }
            }
        }
    }
    #pragma unroll
    for (int e2 = 0; e2 < 2; e2++) {
        float bias = __ldg(&g_bveff[eo0 + e2]) + __ldg(&b_attn[eo0 + e2]);
        float4 v;
        v.x = acc[e2][0] + bias; v.y = acc[e2][1] + bias;
        v.z = acc[e2][2] + bias; v.w = acc[e2][3] + bias;
        v.x = (v.x >= 0.f) ? v.x : 0.2f*v.x;
        v.y = (v.y >= 0.f) ? v.y : 0.2f*v.y;
        v.z = (v.z >= 0.f) ? v.z : 0.2f*v.z;
        v.w = (v.w >= 0.f) ? v.w : 0.2f*v.w;
        *(float4*)&out[(size_t)(b*E_ + eo0 + e2)*HW_ + pix] = v;
    }
}

// ---------------- launch: fork-join DAG across 3 streams ----------------
extern "C" void kernel_launch(void* const* d_in, const int* in_sizes, int n_in,
                              void* d_out, int out_size) {
    const float* contexts = (const float*)d_in[0];
    const float* df       = (const float*)d_in[1];
    const float* w_enc    = (const float*)d_in[2];
    const float* b_enc    = (const float*)d_in[3];
    const float* w_dec    = (const float*)d_in[4];
    const float* b_dec    = (const float*)d_in[5];
    const float* w_agg    = (const float*)d_in[6];
    // d_in[7] = b_agg: cancels in softmax, unused
    const float* w_val    = (const float*)d_in[8];
    const float* b_val    = (const float*)d_in[9];
    const float* w_attn   = (const float*)d_in[10];
    const float* b_attn   = (const float*)d_in[11];
    float* out = (float*)d_out;

    static cudaStream_t s1 = nullptr, s2 = nullptr;
    static cudaEvent_t eF = nullptr, eQ = nullptr, eC = nullptr;
    static bool attrs_set = false;
    if (s1 == nullptr) {
        cudaStreamCreateWithFlags(&s1, cudaStreamNonBlocking);
        cudaStreamCreateWithFlags(&s2, cudaStreamNonBlocking);
        cudaEventCreateWithFlags(&eF, cudaEventDisableTiming);
        cudaEventCreateWithFlags(&eQ, cudaEventDisableTiming);
        cudaEventCreateWithFlags(&eC, cudaEventDisableTiming);
    }

    int smq = Q_TOT32 * 4;
    int smk = KP_TOT32 * 4;
    int smc = CV_TOT32 * 4;
    int sma = (64*KH_STRIDE + 64) * 4;
    if (!attrs_set) {
        cudaFuncSetAttribute(queries_mma,   cudaFuncAttributeMaxDynamicSharedMemorySize, smq);
        cudaFuncSetAttribute(keysproj_mma,  cudaFuncAttributeMaxDynamicSharedMemorySize, smk);
        cudaFuncSetAttribute(conv_mma,      cudaFuncAttributeMaxDynamicSharedMemorySize, smc);
        cudaFuncSetAttribute(attn_kernel,   cudaFuncAttributeMaxDynamicSharedMemorySize, sma);
        attrs_set = true;
    }

    // fork
    cudaEventRecord(eF, 0);
    cudaStreamWaitEvent(s1, eF, 0);
    cudaStreamWaitEvent(s2, eF, 0);

    // branch s1: conv chain (independent of attention path)
    prep_pack<<<144, 256, 0, s1>>>(w_attn, w_val, b_val);
    conv_mma<<<dim3(3, 12, B_*4), 256, smc, s1>>>(df);
    cudaEventRecord(eC, s1);

    // branch s2: queries
    queries_mma<<<dim3(HW_/128, B_), 256, smq, s2>>>(df, w_dec, b_dec);
    cudaEventRecord(eQ, s2);

    // main stream: keysproj -> (join queries) attn -> (join conv) out
    keysproj_mma<<<dim3(HW_/256, K_*B_), 256, smk>>>(contexts, w_enc, b_enc, w_attn);
    cudaStreamWaitEvent(0, eQ, 0);
    attn_kernel<<<dim3(3, 12, K_*B_), 256, sma>>>(w_agg);
    cudaStreamWaitEvent(0, eC, 0);
    out_kernel<<<(B_*HW_)/32, 256>>>(b_attn, out);
}